// round 2
// baseline (speedup 1.0000x reference)
#include <cuda_runtime.h>

#define NN 100000
#define EE 1200000
#define ET (EE + NN)

// ---------------- scratch (static device memory: allocation-free) ----------
__device__ float g_xw[NN * 128];   // post-GEMM features (xw), per layer
__device__ float g_h[NN * 128];    // aggregated layer output (GEMM input)
__device__ float g_ssrc[NN * 4];
__device__ float g_sdst[NN * 4];
__device__ int   g_cnt[NN];
__device__ int   g_off[NN + 1];
__device__ int   g_cur[NN];
__device__ int   g_csr[ET];
__device__ int   g_bsum[128];

// ---------------- CSR build -------------------------------------------------
__global__ void k_init_cnt() {
    int i = blockIdx.x * blockDim.x + threadIdx.x;
    if (i < NN) g_cnt[i] = 1;  // self-loop
}

__global__ void k_count(const int* __restrict__ ei) {
    int e = blockIdx.x * blockDim.x + threadIdx.x;
    if (e < EE) atomicAdd(&g_cnt[ei[EE + e]], 1);
}

__global__ void k_scan1() {  // 98 blocks x 1024
    __shared__ int s[1024];
    int i = blockIdx.x * 1024 + threadIdx.x;
    int v = (i < NN) ? g_cnt[i] : 0;
    s[threadIdx.x] = v;
    __syncthreads();
    for (int d = 1; d < 1024; d <<= 1) {
        int t = (threadIdx.x >= d) ? s[threadIdx.x - d] : 0;
        __syncthreads();
        s[threadIdx.x] += t;
        __syncthreads();
    }
    if (i < NN) g_off[i] = s[threadIdx.x] - v;  // exclusive
    if (threadIdx.x == 1023) g_bsum[blockIdx.x] = s[1023];
}

__global__ void k_scan2() {  // 1 block x 128
    __shared__ int s[128];
    int v = (threadIdx.x < 98) ? g_bsum[threadIdx.x] : 0;
    s[threadIdx.x] = v;
    __syncthreads();
    for (int d = 1; d < 128; d <<= 1) {
        int t = (threadIdx.x >= d) ? s[threadIdx.x - d] : 0;
        __syncthreads();
        s[threadIdx.x] += t;
        __syncthreads();
    }
    g_bsum[threadIdx.x] = s[threadIdx.x] - v;  // exclusive
}

__global__ void k_scan3() {
    int i = blockIdx.x * blockDim.x + threadIdx.x;
    if (i < NN) {
        int o = g_off[i] + g_bsum[i >> 10];
        g_off[i] = o;
        g_cur[i] = o;
    }
    if (i == 0) g_off[NN] = ET;
}

__global__ void k_fill(const int* __restrict__ ei) {
    int e = blockIdx.x * blockDim.x + threadIdx.x;
    if (e < EE) {
        int s = ei[e], d = ei[EE + e];
        g_csr[atomicAdd(&g_cur[d], 1)] = s;
    } else if (e < ET) {
        int v = e - EE;
        g_csr[atomicAdd(&g_cur[v], 1)] = v;
    }
}

// ---------------- GEMM: g_xw = X @ W   (X: [NN,128], W: [128,128]) ---------
__launch_bounds__(256, 2)
__global__ void k_gemm(const float* __restrict__ Xext, const float* __restrict__ W,
                       int use_h) {
    extern __shared__ float sm[];
    float* sW = sm;           // 128*128 = 16384 floats (64KB)
    float* sX = sm + 16384;   // 64*128  =  8192 floats (32KB)
    const float* X = use_h ? (const float*)g_h : Xext;

    for (int i = threadIdx.x; i < 4096; i += 256)
        ((float4*)sW)[i] = ((const float4*)W)[i];

    int row0 = blockIdx.x * 64;
    for (int i = threadIdx.x; i < 2048; i += 256) {
        int r = i >> 5, c = i & 31;
        int gr = row0 + r;
        float4 v = make_float4(0.f, 0.f, 0.f, 0.f);
        if (gr < NN) v = ((const float4*)X)[gr * 32 + c];
        ((float4*)sX)[i] = v;
    }
    __syncthreads();

    int tx = threadIdx.x & 31, ty = threadIdx.x >> 5;
    int c0 = tx * 4, r0 = ty * 8;
    float acc[8][4];
#pragma unroll
    for (int ri = 0; ri < 8; ri++) {
        acc[ri][0] = 0.f; acc[ri][1] = 0.f; acc[ri][2] = 0.f; acc[ri][3] = 0.f;
    }
#pragma unroll 4
    for (int k = 0; k < 128; k++) {
        float4 b = *(const float4*)&sW[k * 128 + c0];
#pragma unroll
        for (int ri = 0; ri < 8; ri++) {
            float a = sX[(r0 + ri) * 128 + k];
            acc[ri][0] += a * b.x;
            acc[ri][1] += a * b.y;
            acc[ri][2] += a * b.z;
            acc[ri][3] += a * b.w;
        }
    }
#pragma unroll
    for (int ri = 0; ri < 8; ri++) {
        int gr = row0 + r0 + ri;
        if (gr < NN)
            ((float4*)g_xw)[gr * 32 + tx] =
                make_float4(acc[ri][0], acc[ri][1], acc[ri][2], acc[ri][3]);
    }
}

// ---------------- per-node attention half-scores ---------------------------
__global__ void k_score(const float* __restrict__ asrc, const float* __restrict__ adst) {
    int g = blockIdx.x * blockDim.x + threadIdx.x;
    int v = g >> 5, lane = g & 31;
    if (v >= NN) return;
    float4 x = ((const float4*)g_xw)[v * 32 + lane];
    float4 a = ((const float4*)asrc)[lane];
    float4 d = ((const float4*)adst)[lane];
    float ps = x.x * a.x + x.y * a.y + x.z * a.z + x.w * a.w;
    float pd = x.x * d.x + x.y * d.y + x.z * d.z + x.w * d.w;
#pragma unroll
    for (int o = 1; o < 8; o <<= 1) {
        ps += __shfl_xor_sync(0xffffffffu, ps, o);
        pd += __shfl_xor_sync(0xffffffffu, pd, o);
    }
    if ((lane & 7) == 0) {
        g_ssrc[v * 4 + (lane >> 3)] = ps;
        g_sdst[v * 4 + (lane >> 3)] = pd;
    }
}

// ---------------- warp-per-node softmax aggregation ------------------------
// out[v,h,c] = (sum_e exp(alpha_e - m_h) * xw[u_e,h,c]) / (sum_e exp(alpha_e - m_h))
template <bool LAST>
__global__ void k_agg(const float* __restrict__ bias, float* __restrict__ outp) {
    int g = blockIdx.x * blockDim.x + threadIdx.x;
    int v = g >> 5, lane = g & 31;
    if (v >= NN) return;

    int offv = g_off[v];
    int deg = g_off[v + 1] - offv;

    // pass 1: per-head max (lanes grouped 4-wide over heads, 8 edges in flight)
    int h1 = lane & 3;
    float sd1 = g_sdst[v * 4 + h1];
    float m = -1e30f;
    for (int base = 0; base < deg; base += 8) {
        int e = base + (lane >> 2);
        if (e < deg) {
            int u = g_csr[offv + e];
            float a = g_ssrc[u * 4 + h1] + sd1;
            a = (a > 0.f) ? a : 0.2f * a;
            m = fmaxf(m, a);
        }
    }
    m = fmaxf(m, __shfl_xor_sync(0xffffffffu, m, 4));
    m = fmaxf(m, __shfl_xor_sync(0xffffffffu, m, 8));
    m = fmaxf(m, __shfl_xor_sync(0xffffffffu, m, 16));
    // lane h (h<4) now holds max for head h

    // pass 2: fused exp + gather + accumulate. lane handles cols [lane*4, lane*4+4)
    int h2 = lane >> 3;
    float mh = __shfl_sync(0xffffffffu, m, h2);
    float sd2 = g_sdst[v * 4 + h2];
    float4 acc = make_float4(0.f, 0.f, 0.f, 0.f);
    float dsum = 0.f;
    for (int e = 0; e < deg; e++) {
        int u = g_csr[offv + e];
        float a = g_ssrc[u * 4 + h2] + sd2;
        a = (a > 0.f) ? a : 0.2f * a;
        float ex = __expf(a - mh);
        dsum += ex;
        float4 xu = ((const float4*)g_xw)[u * 32 + lane];
        acc.x += ex * xu.x;
        acc.y += ex * xu.y;
        acc.z += ex * xu.z;
        acc.w += ex * xu.w;
    }
    float inv = 1.f / dsum;
    acc.x *= inv; acc.y *= inv; acc.z *= inv; acc.w *= inv;

    if (!LAST) {
        float4 bv = ((const float4*)bias)[lane];
        float4 o;
        o.x = acc.x + bv.x; o.y = acc.y + bv.y;
        o.z = acc.z + bv.z; o.w = acc.w + bv.w;
        o.x = o.x > 0.f ? o.x : expm1f(o.x);
        o.y = o.y > 0.f ? o.y : expm1f(o.y);
        o.z = o.z > 0.f ? o.z : expm1f(o.z);
        o.w = o.w > 0.f ? o.w : expm1f(o.w);
        ((float4*)g_h)[v * 32 + lane] = o;
    } else {
        // mean over 4 heads: lanes {l, l+8, l+16, l+24} hold same within-head cols
        acc.x += __shfl_xor_sync(0xffffffffu, acc.x, 8);
        acc.y += __shfl_xor_sync(0xffffffffu, acc.y, 8);
        acc.z += __shfl_xor_sync(0xffffffffu, acc.z, 8);
        acc.w += __shfl_xor_sync(0xffffffffu, acc.w, 8);
        acc.x += __shfl_xor_sync(0xffffffffu, acc.x, 16);
        acc.y += __shfl_xor_sync(0xffffffffu, acc.y, 16);
        acc.z += __shfl_xor_sync(0xffffffffu, acc.z, 16);
        acc.w += __shfl_xor_sync(0xffffffffu, acc.w, 16);
        if (lane < 8) {
            float4 bv = ((const float4*)bias)[lane];
            float4 o = make_float4(acc.x * 0.25f + bv.x, acc.y * 0.25f + bv.y,
                                   acc.z * 0.25f + bv.z, acc.w * 0.25f + bv.w);
            ((float4*)outp)[v * 8 + lane] = o;
        }
    }
}

// ---------------- driver ----------------------------------------------------
extern "C" void kernel_launch(void* const* d_in, const int* in_sizes, int n_in,
                              void* d_out, int out_size) {
    const float* x   = (const float*)d_in[0];
    const int*   ei  = (const int*)d_in[1];
    const float* W1  = (const float*)d_in[2];
    const float* as1 = (const float*)d_in[3];
    const float* ad1 = (const float*)d_in[4];
    const float* b1  = (const float*)d_in[5];
    const float* W2  = (const float*)d_in[6];
    const float* as2 = (const float*)d_in[7];
    const float* ad2 = (const float*)d_in[8];
    const float* b2  = (const float*)d_in[9];
    const float* W3  = (const float*)d_in[10];
    const float* as3 = (const float*)d_in[11];
    const float* ad3 = (const float*)d_in[12];
    const float* b3  = (const float*)d_in[13];
    float* out = (float*)d_out;

    cudaFuncSetAttribute(k_gemm, cudaFuncAttributeMaxDynamicSharedMemorySize, 98304);

    // CSR by destination (rebuilt every call: deterministic work, capture-safe)
    k_init_cnt<<<(NN + 255) / 256, 256>>>();
    k_count<<<(EE + 255) / 256, 256>>>(ei);
    k_scan1<<<98, 1024>>>();
    k_scan2<<<1, 128>>>();
    k_scan3<<<(NN + 255) / 256, 256>>>();
    k_fill<<<(ET + 255) / 256, 256>>>(ei);

    const int GB = (NN + 63) / 64;   // 1563
    const int WB = NN / 8;           // 12500 blocks of 8 warps (warp per node)

    // layer 1
    k_gemm<<<GB, 256, 98304>>>(x, W1, 0);
    k_score<<<WB, 256>>>(as1, ad1);
    k_agg<false><<<WB, 256>>>(b1, nullptr);
    // layer 2
    k_gemm<<<GB, 256, 98304>>>(nullptr, W2, 1);
    k_score<<<WB, 256>>>(as2, ad2);
    k_agg<false><<<WB, 256>>>(b2, nullptr);
    // layer 3 (mean over heads)
    k_gemm<<<GB, 256, 98304>>>(nullptr, W3, 1);
    k_score<<<WB, 256>>>(as3, ad3);
    k_agg<true><<<WB, 256>>>(b3, out);
}